// round 13
// baseline (speedup 1.0000x reference)
#include <cuda_runtime.h>
#include <cuda_fp16.h>
#include <cstdint>
#include <cstdio>

#define B_    1024
#define V_    50257
#define E_    128
#define NBK   786                 // ceil(V/64)
#define VPAD  (NBK*64)            // 50304

// ---------------- device scratch ----------------
__device__ int    g_idx[B_];
__device__ __half g_qh[B_*E_];
__device__ __half g_negh[(size_t)VPAD*E_];
__device__ float  g_pmax[(size_t)B_*NBK];
__device__ float  g_psum[(size_t)B_*NBK];
__device__ float  g_lse[B_];

// ---------------- helpers ----------------
__device__ __forceinline__ uint32_t smem_u32(const void* p){
    uint32_t a;
    asm("{ .reg .u64 t; cvta.to.shared.u64 t, %1; cvt.u32.u64 %0, t; }" : "=r"(a) : "l"(p));
    return a;
}
__device__ __forceinline__ uint32_t sw128(uint32_t off){ return off ^ ((off >> 3) & 0x70); }

__device__ __forceinline__ void lse_merge(float& m, float& s, float m2, float s2){
    float M = fmaxf(m, m2);
    s = s*__expf(m - M) + s2*__expf(m2 - M);
    m = M;
}

__device__ __forceinline__ void mma_f16(float c[4], const uint32_t a[4],
                                        uint32_t b0, uint32_t b1){
    asm volatile(
        "mma.sync.aligned.m16n8k16.row.col.f32.f16.f16.f32 "
        "{%0,%1,%2,%3}, {%4,%5,%6,%7}, {%8,%9}, {%0,%1,%2,%3};\n"
        : "+f"(c[0]), "+f"(c[1]), "+f"(c[2]), "+f"(c[3])
        : "r"(a[0]), "r"(a[1]), "r"(a[2]), "r"(a[3]), "r"(b0), "r"(b1));
}

__device__ __forceinline__ void ldsm_x4(uint32_t& r0, uint32_t& r1,
                                        uint32_t& r2, uint32_t& r3, uint32_t addr){
    asm volatile("ldmatrix.sync.aligned.m8n8.x4.shared.b16 {%0,%1,%2,%3}, [%4];"
                 : "=r"(r0), "=r"(r1), "=r"(r2), "=r"(r3) : "r"(addr));
}

// ---------------- kernel 1: one-hot index extraction ----------------
__global__ void k_findidx(const float4* __restrict__ xs){
    long n4 = (long)B_*V_/4;
    for (long i = (long)blockIdx.x*blockDim.x + threadIdx.x; i < n4;
         i += (long)gridDim.x*blockDim.x){
        float4 v = __ldcs(xs + i);
        if (v.x!=0.f || v.y!=0.f || v.z!=0.f || v.w!=0.f){
            long base = i*4;
            if (v.x!=0.f){ long f=base;   g_idx[f/V_] = (int)(f%V_); }
            if (v.y!=0.f){ long f=base+1; g_idx[f/V_] = (int)(f%V_); }
            if (v.z!=0.f){ long f=base+2; g_idx[f/V_] = (int)(f%V_); }
            if (v.w!=0.f){ long f=base+3; g_idx[f/V_] = (int)(f%V_); }
        }
    }
}

// ---------------- kernel 2: NEG -> fp16, zero-padded to VPAD rows ----------------
__global__ void k_prep(const float* __restrict__ neg){
    long i4 = (long)blockIdx.x*blockDim.x + threadIdx.x;   // one float4 = 4 elems
    if (i4 >= (long)VPAD*32) return;
    long e = i4*4;
    int row = (int)(e >> 7);
    float4 v = make_float4(0.f,0.f,0.f,0.f);
    if (row < V_) v = *(const float4*)(neg + e);
    __half2 a = __floats2half2_rn(v.x, v.y);
    __half2 b = __floats2half2_rn(v.z, v.w);
    uint2 p;
    p.x = *(uint32_t*)&a;
    p.y = *(uint32_t*)&b;
    *(uint2*)((char*)g_negh + e*2) = p;
}

// ---------------- kernel 3: q[b] = EMBEDM[idx[b]] @ metric -> fp16 ----------------
__global__ void k_q(const float* __restrict__ emb, const float* __restrict__ metric){
    __shared__ float se[E_];
    int b = blockIdx.x, t = threadIdx.x;
    int id = g_idx[b];
    se[t] = emb[(size_t)id*E_ + t];
    __syncthreads();
    float acc = 0.f;
    #pragma unroll 16
    for (int k = 0; k < E_; k++) acc = fmaf(se[k], metric[k*E_ + t], acc);
    g_qh[b*E_ + t] = __float2half_rn(acc);
}

// ---------------- GEMM pass: CTA tile 128(M)x64(N), warp tile 32x32 ----------------
// smem: As 2 chunks [128][64]fp16 SW128 at 0 (32KB), Bs 2 chunks [64][64]fp16 at 32768 (16KB).
// EPI=1 reuses smem as fp32 stage [128][68] (34.8KB).
#define STG_STRIDE 68
#define SMEM_REQ   49152

template<int EPI>
__global__ __launch_bounds__(256, 3) void k_pass(float* __restrict__ out){
    extern __shared__ char smc[];
    const uint32_t sb = smem_u32(smc);
    const int t    = threadIdx.x;
    const int lane = t & 31, wid = t >> 5;
    const int wm   = wid & 3;            // 4 warps in M (32 rows each)
    const int wn   = wid >> 2;           // 2 warps in N (32 cols each)
    const int g    = lane >> 2, t4 = lane & 3;
    const int mb = blockIdx.x, nb = blockIdx.y;
    const int m0 = mb*128, v0 = nb*64;

    // ---- cp.async loads (16B granules, no guards) ----
    // A: 128 rows x 128 k -> 2 chunks of [128][64] (16KB each)
    #pragma unroll
    for (int j = 0; j < 8; j++){
        int id = t + j*256;                   // 0..2047
        int chunk = id >> 10, rem = id & 1023;
        int row = rem >> 3, c16 = rem & 7;
        const __half* gp = g_qh + (size_t)(m0 + row)*E_ + chunk*64 + c16*8;
        uint32_t sa = sb + chunk*16384 + sw128(row*128 + c16*16);
        asm volatile("cp.async.cg.shared.global [%0], [%1], 16;" :: "r"(sa), "l"(gp));
    }
    // B: 64 rows x 128 k -> 2 chunks of [64][64] (8KB each) at 32768
    #pragma unroll
    for (int j = 0; j < 4; j++){
        int id = t + j*256;                   // 0..1023
        int chunk = id >> 9, rem = id & 511;
        int row = rem >> 3, c16 = rem & 7;
        const __half* gp = g_negh + (size_t)(v0 + row)*E_ + chunk*64 + c16*8;
        uint32_t sa = sb + 32768 + chunk*8192 + sw128(row*128 + c16*16);
        asm volatile("cp.async.cg.shared.global [%0], [%1], 16;" :: "r"(sa), "l"(gp));
    }
    asm volatile("cp.async.commit_group;\n cp.async.wait_group 0;" ::: "memory");
    __syncthreads();

    float acc[2][4][4];
    #pragma unroll
    for (int mi = 0; mi < 2; mi++)
        #pragma unroll
        for (int ni = 0; ni < 4; ni++)
            #pragma unroll
            for (int c = 0; c < 4; c++) acc[mi][ni][c] = 0.f;

    // ---- 8 k16-steps ----
    #pragma unroll
    for (int ks = 0; ks < 8; ks++){
        const int chunk = ks >> 2, k8 = ks & 3;
        const uint32_t abase = sb + chunk*16384;
        const uint32_t bbase = sb + 32768 + chunk*8192;

        uint32_t a[2][4];
        #pragma unroll
        for (int mi = 0; mi < 2; mi++){
            int row = wm*32 + mi*16 + (lane & 7) + ((lane >> 3) & 1)*8;
            int gran = k8*2 + (lane >> 4);
            ldsm_x4(a[mi][0], a[mi][1], a[mi][2], a[mi][3],
                    abase + sw128(row*128 + gran*16));
        }
        uint32_t bb[4][2];
        #pragma unroll
        for (int p = 0; p < 2; p++){
            int mtx = lane >> 3;
            int n = wn*32 + p*16 + ((mtx >> 1) << 3) + (lane & 7);
            int gran = k8*2 + (mtx & 1);
            ldsm_x4(bb[2*p][0], bb[2*p][1], bb[2*p+1][0], bb[2*p+1][1],
                    bbase + sw128(n*128 + gran*16));
        }
        #pragma unroll
        for (int mi = 0; mi < 2; mi++)
            #pragma unroll
            for (int ni = 0; ni < 4; ni++)
                mma_f16(acc[mi][ni], a[mi], bb[ni][0], bb[ni][1]);
    }

    // ---- epilogue ----
    if (EPI == 0){
        float rm[2][2] = {{-1e30f,-1e30f},{-1e30f,-1e30f}};
        float rs[2][2] = {{0.f,0.f},{0.f,0.f}};
        #pragma unroll
        for (int mi = 0; mi < 2; mi++)
            #pragma unroll
            for (int ni = 0; ni < 4; ni++){
                int col0 = v0 + wn*32 + ni*8 + 2*t4;
                if (col0   < V_){ rm[mi][0] = fmaxf(rm[mi][0], acc[mi][ni][0]);
                                  rm[mi][1] = fmaxf(rm[mi][1], acc[mi][ni][2]); }
                if (col0+1 < V_){ rm[mi][0] = fmaxf(rm[mi][0], acc[mi][ni][1]);
                                  rm[mi][1] = fmaxf(rm[mi][1], acc[mi][ni][3]); }
            }
        #pragma unroll
        for (int mi = 0; mi < 2; mi++)
            #pragma unroll
            for (int ni = 0; ni < 4; ni++){
                int col0 = v0 + wn*32 + ni*8 + 2*t4;
                if (col0   < V_){ rs[mi][0] += __expf(acc[mi][ni][0] - rm[mi][0]);
                                  rs[mi][1] += __expf(acc[mi][ni][2] - rm[mi][1]); }
                if (col0+1 < V_){ rs[mi][0] += __expf(acc[mi][ni][1] - rm[mi][0]);
                                  rs[mi][1] += __expf(acc[mi][ni][3] - rm[mi][1]); }
            }
        #pragma unroll
        for (int mi = 0; mi < 2; mi++)
            #pragma unroll
            for (int h = 0; h < 2; h++)
                #pragma unroll
                for (int off = 1; off <= 2; off <<= 1){
                    float m2 = __shfl_xor_sync(0xffffffffu, rm[mi][h], off);
                    float s2 = __shfl_xor_sync(0xffffffffu, rs[mi][h], off);
                    lse_merge(rm[mi][h], rs[mi][h], m2, s2);
                }
        __syncthreads();
        float* red = (float*)smc;   // [128 rows][2 wn][2]
        if (t4 == 0){
            #pragma unroll
            for (int mi = 0; mi < 2; mi++)
                #pragma unroll
                for (int h = 0; h < 2; h++){
                    int rl = wm*32 + mi*16 + h*8 + g;
                    red[rl*4 + wn*2 + 0] = rm[mi][h];
                    red[rl*4 + wn*2 + 1] = rs[mi][h];
                }
        }
        __syncthreads();
        if (t < 128){
            float m = red[t*4 + 0], s = red[t*4 + 1];
            lse_merge(m, s, red[t*4 + 2], red[t*4 + 3]);
            g_pmax[(size_t)(m0 + t)*NBK + nb] = m;
            g_psum[(size_t)(m0 + t)*NBK + nb] = s;
        }
    } else {
        // ---- staged store: smem [128][STG_STRIDE] fp32, subtract lse at STS ----
        float l[2][2];
        #pragma unroll
        for (int mi = 0; mi < 2; mi++){
            l[mi][0] = g_lse[m0 + wm*32 + mi*16 + g];
            l[mi][1] = g_lse[m0 + wm*32 + mi*16 + 8 + g];
        }
        float* stage = (float*)smc;
        __syncthreads();               // mainloop smem reads complete before overwrite
        #pragma unroll
        for (int mi = 0; mi < 2; mi++){
            int rowL0 = wm*32 + mi*16 + g;
            int rowL1 = rowL0 + 8;
            #pragma unroll
            for (int ni = 0; ni < 4; ni++){
                int colL = wn*32 + ni*8 + 2*t4;
                *(float2*)(stage + rowL0*STG_STRIDE + colL) =
                    make_float2(acc[mi][ni][0]-l[mi][0], acc[mi][ni][1]-l[mi][0]);
                *(float2*)(stage + rowL1*STG_STRIDE + colL) =
                    make_float2(acc[mi][ni][2]-l[mi][1], acc[mi][ni][3]-l[mi][1]);
            }
        }
        __syncthreads();
        // coalesced writes: warp wid owns rows wid*16..wid*16+15, 2x128B per row
        const int ncols = min(64, V_ - v0);
        float* obase = out + (size_t)(m0 + wid*16)*V_ + v0;
        #pragma unroll
        for (int i = 0; i < 16; i++){
            const float* srow = stage + (wid*16 + i)*STG_STRIDE;
            #pragma unroll
            for (int j = 0; j < 2; j++){
                int col = j*32 + lane;
                if (col < ncols) obase[col] = srow[col];
            }
            obase += V_;
        }
    }
}

// ---------------- kernel: combine partials -> lse per row ----------------
__global__ void k_reduce(){
    int r = blockIdx.x, t = threadIdx.x;   // 128 threads
    float m = -1e30f, s = 0.f;
    for (int p = t; p < NBK; p += 128)
        lse_merge(m, s, g_pmax[(size_t)r*NBK + p], g_psum[(size_t)r*NBK + p]);
    #pragma unroll
    for (int off = 16; off >= 1; off >>= 1){
        float m2 = __shfl_xor_sync(0xffffffffu, m, off);
        float s2 = __shfl_xor_sync(0xffffffffu, s, off);
        lse_merge(m, s, m2, s2);
    }
    __shared__ float sm_[4], ss_[4];
    int w = t >> 5;
    if ((t & 31) == 0){ sm_[w] = m; ss_[w] = s; }
    __syncthreads();
    if (t == 0){
        for (int w2 = 1; w2 < 4; w2++) lse_merge(m, s, sm_[w2], ss_[w2]);
        g_lse[r] = m + logf(s);
    }
}

// ---------------- launch ----------------
extern "C" void kernel_launch(void* const* d_in, const int* in_sizes, int n_in,
                              void* d_out, int out_size){
    const float* xs     = (const float*)d_in[0];   // [B, V]
    const float* metric = (const float*)d_in[1];   // [E, E]
    const float* emb    = (const float*)d_in[2];   // [V, E]
    const float* neg    = (const float*)d_in[3];   // [V, E]
    float* out = (float*)d_out;

    cudaFuncSetAttribute((const void*)k_pass<0>,
                         cudaFuncAttributeMaxDynamicSharedMemorySize, SMEM_REQ);
    cudaFuncSetAttribute((const void*)k_pass<1>,
                         cudaFuncAttributeMaxDynamicSharedMemorySize, SMEM_REQ);

    k_findidx<<<1184, 256>>>((const float4*)xs);
    k_prep<<<(VPAD*32 + 255)/256, 256>>>(neg);
    k_q<<<B_, E_>>>(emb, metric);
    dim3 grid(B_/128, NBK);     // mb fastest -> 8 CTAs share each B tile in L2
    k_pass<0><<<grid, 256, SMEM_REQ>>>(out);
    k_reduce<<<B_, 128>>>();
    k_pass<1><<<grid, 256, SMEM_REQ>>>(out);
}

// round 17
// speedup vs baseline: 1.0292x; 1.0292x over previous
#include <cuda_runtime.h>
#include <cuda_fp16.h>
#include <cstdint>
#include <cstdio>

#define B_    1024
#define V_    50257
#define E_    128
#define NBK   393                 // ceil(V/128)
#define VPAD  (NBK*128)           // 50304

// ---------------- device scratch ----------------
__device__ int    g_idx[B_];
__device__ __half g_qh[B_*E_];
__device__ __half g_negh[(size_t)VPAD*E_];
__device__ __half g_s[(size_t)B_*VPAD];     // fp16 score cache (103MB)
__device__ float  g_pmax[(size_t)B_*NBK];
__device__ float  g_psum[(size_t)B_*NBK];
__device__ float  g_lse[B_];

// ---------------- helpers ----------------
__device__ __forceinline__ uint32_t smem_u32(const void* p){
    uint32_t a;
    asm("{ .reg .u64 t; cvta.to.shared.u64 t, %1; cvt.u32.u64 %0, t; }" : "=r"(a) : "l"(p));
    return a;
}
__device__ __forceinline__ uint32_t sw128(uint32_t off){ return off ^ ((off >> 3) & 0x70); }

__device__ __forceinline__ void lse_merge(float& m, float& s, float m2, float s2){
    float M = fmaxf(m, m2);
    s = s*__expf(m - M) + s2*__expf(m2 - M);
    m = M;
}

__device__ __forceinline__ void mma_f16(float c[4], const uint32_t a[4],
                                        uint32_t b0, uint32_t b1){
    asm volatile(
        "mma.sync.aligned.m16n8k16.row.col.f32.f16.f16.f32 "
        "{%0,%1,%2,%3}, {%4,%5,%6,%7}, {%8,%9}, {%0,%1,%2,%3};\n"
        : "+f"(c[0]), "+f"(c[1]), "+f"(c[2]), "+f"(c[3])
        : "r"(a[0]), "r"(a[1]), "r"(a[2]), "r"(a[3]), "r"(b0), "r"(b1));
}

__device__ __forceinline__ void ldsm_x4(uint32_t& r0, uint32_t& r1,
                                        uint32_t& r2, uint32_t& r3, uint32_t addr){
    asm volatile("ldmatrix.sync.aligned.m8n8.x4.shared.b16 {%0,%1,%2,%3}, [%4];"
                 : "=r"(r0), "=r"(r1), "=r"(r2), "=r"(r3) : "r"(addr));
}

// ---------------- kernel 1: fused xs scan (one-hot idx) + NEG->fp16 prep ----------------
#define SCAN_BLOCKS 1184
#define PREP_BLOCKS 160
__global__ void k_scanprep(const float4* __restrict__ xs, const float* __restrict__ neg){
    int b = blockIdx.x, t = threadIdx.x;
    if (b < SCAN_BLOCKS){
        long n4 = (long)B_*V_/4;
        for (long i = (long)b*blockDim.x + t; i < n4; i += (long)SCAN_BLOCKS*blockDim.x){
            float4 v = __ldcs(xs + i);
            if (v.x!=0.f || v.y!=0.f || v.z!=0.f || v.w!=0.f){
                long base = i*4;
                if (v.x!=0.f){ long f=base;   g_idx[f/V_] = (int)(f%V_); }
                if (v.y!=0.f){ long f=base+1; g_idx[f/V_] = (int)(f%V_); }
                if (v.z!=0.f){ long f=base+2; g_idx[f/V_] = (int)(f%V_); }
                if (v.w!=0.f){ long f=base+3; g_idx[f/V_] = (int)(f%V_); }
            }
        }
    } else {
        long np = (long)VPAD*32;    // float4 count
        for (long i4 = (long)(b - SCAN_BLOCKS)*blockDim.x + t; i4 < np;
             i4 += (long)PREP_BLOCKS*blockDim.x){
            long e = i4*4;
            int row = (int)(e >> 7);
            float4 v = make_float4(0.f,0.f,0.f,0.f);
            if (row < V_) v = *(const float4*)(neg + e);
            __half2 a = __floats2half2_rn(v.x, v.y);
            __half2 c = __floats2half2_rn(v.z, v.w);
            uint2 p;
            p.x = *(uint32_t*)&a;
            p.y = *(uint32_t*)&c;
            *(uint2*)((char*)g_negh + e*2) = p;
        }
    }
}

// ---------------- kernel 2: q[b] = EMBEDM[idx[b]] @ metric -> fp16 ----------------
__global__ void k_q(const float* __restrict__ emb, const float* __restrict__ metric){
    __shared__ float se[E_];
    int b = blockIdx.x, t = threadIdx.x;
    int id = g_idx[b];
    se[t] = emb[(size_t)id*E_ + t];
    __syncthreads();
    float acc = 0.f;
    #pragma unroll 16
    for (int k = 0; k < E_; k++) acc = fmaf(se[k], metric[k*E_ + t], acc);
    g_qh[b*E_ + t] = __float2half_rn(acc);
}

// ---------------- GEMM pass: 128x128 tile, warp 32x64; writes fp16 scores + partials ----
// smem mainloop: As 2 chunks [128][64]fp16 SW128 at 0, Bs same at 32768 (64KB).
// epilogue: stage __half [128][136] (34816B) + red[] at 34816.
#define STG_H  136
#define SMEM_REQ 66560

__global__ __launch_bounds__(256, 2) void k_pass0(){
    extern __shared__ char smc[];
    const uint32_t sb = smem_u32(smc);
    const int t    = threadIdx.x;
    const int lane = t & 31, wid = t >> 5;
    const int wm   = wid & 3;            // 4 warps in M (32 rows each)
    const int wn   = wid >> 2;           // 2 warps in N (64 cols each)
    const int g    = lane >> 2, t4 = lane & 3;
    const int mb = blockIdx.x, nb = blockIdx.y;
    const int m0 = mb*128, v0 = nb*128;

    // ---- cp.async loads: A and B fp16, 16B granules ----
    #pragma unroll
    for (int j = 0; j < 8; j++){
        int id = t + j*256;
        int chunk = id >> 10, rem = id & 1023;
        int row = rem >> 3, c16 = rem & 7;
        const __half* gp = g_qh + (size_t)(m0 + row)*E_ + chunk*64 + c16*8;
        uint32_t sa = sb + chunk*16384 + sw128(row*128 + c16*16);
        asm volatile("cp.async.cg.shared.global [%0], [%1], 16;" :: "r"(sa), "l"(gp));
    }
    #pragma unroll
    for (int j = 0; j < 8; j++){
        int id = t + j*256;
        int chunk = id >> 10, rem = id & 1023;
        int row = rem >> 3, c16 = rem & 7;
        const __half* gp = g_negh + (size_t)(v0 + row)*E_ + chunk*64 + c16*8;
        uint32_t sa = sb + 32768 + chunk*16384 + sw128(row*128 + c16*16);
        asm volatile("cp.async.cg.shared.global [%0], [%1], 16;" :: "r"(sa), "l"(gp));
    }
    asm volatile("cp.async.commit_group;\n cp.async.wait_group 0;" ::: "memory");
    __syncthreads();

    float acc[2][8][4];
    #pragma unroll
    for (int mi = 0; mi < 2; mi++)
        #pragma unroll
        for (int ni = 0; ni < 8; ni++)
            #pragma unroll
            for (int c = 0; c < 4; c++) acc[mi][ni][c] = 0.f;

    #pragma unroll
    for (int ks = 0; ks < 8; ks++){
        const int chunk = ks >> 2, k8 = ks & 3;
        const uint32_t abase = sb + chunk*16384;
        const uint32_t bbase = sb + 32768 + chunk*16384;

        uint32_t a[2][4];
        #pragma unroll
        for (int mi = 0; mi < 2; mi++){
            int row = wm*32 + mi*16 + (lane & 7) + ((lane >> 3) & 1)*8;
            int gran = k8*2 + (lane >> 4);
            ldsm_x4(a[mi][0], a[mi][1], a[mi][2], a[mi][3],
                    abase + sw128(row*128 + gran*16));
        }
        uint32_t bb[8][2];
        #pragma unroll
        for (int p = 0; p < 4; p++){
            int mtx = lane >> 3;
            int n = wn*64 + p*16 + ((mtx >> 1) << 3) + (lane & 7);
            int gran = k8*2 + (mtx & 1);
            ldsm_x4(bb[2*p][0], bb[2*p][1], bb[2*p+1][0], bb[2*p+1][1],
                    bbase + sw128(n*128 + gran*16));
        }
        #pragma unroll
        for (int mi = 0; mi < 2; mi++)
            #pragma unroll
            for (int ni = 0; ni < 8; ni++)
                mma_f16(acc[mi][ni], a[mi], bb[ni][0], bb[ni][1]);
    }

    // ---- epilogue: lse partials + fp16 score staging + coalesced STG ----
    float rm[2][2] = {{-1e30f,-1e30f},{-1e30f,-1e30f}};
    float rs[2][2] = {{0.f,0.f},{0.f,0.f}};
    #pragma unroll
    for (int mi = 0; mi < 2; mi++)
        #pragma unroll
        for (int ni = 0; ni < 8; ni++){
            int col0 = v0 + wn*64 + ni*8 + 2*t4;
            if (col0   < V_){ rm[mi][0] = fmaxf(rm[mi][0], acc[mi][ni][0]);
                              rm[mi][1] = fmaxf(rm[mi][1], acc[mi][ni][2]); }
            if (col0+1 < V_){ rm[mi][0] = fmaxf(rm[mi][0], acc[mi][ni][1]);
                              rm[mi][1] = fmaxf(rm[mi][1], acc[mi][ni][3]); }
        }
    #pragma unroll
    for (int mi = 0; mi < 2; mi++)
        #pragma unroll
        for (int ni = 0; ni < 8; ni++){
            int col0 = v0 + wn*64 + ni*8 + 2*t4;
            if (col0   < V_){ rs[mi][0] += __expf(acc[mi][ni][0] - rm[mi][0]);
                              rs[mi][1] += __expf(acc[mi][ni][2] - rm[mi][1]); }
            if (col0+1 < V_){ rs[mi][0] += __expf(acc[mi][ni][1] - rm[mi][0]);
                              rs[mi][1] += __expf(acc[mi][ni][3] - rm[mi][1]); }
        }
    #pragma unroll
    for (int mi = 0; mi < 2; mi++)
        #pragma unroll
        for (int h = 0; h < 2; h++)
            #pragma unroll
            for (int off = 1; off <= 2; off <<= 1){
                float m2 = __shfl_xor_sync(0xffffffffu, rm[mi][h], off);
                float s2 = __shfl_xor_sync(0xffffffffu, rs[mi][h], off);
                lse_merge(rm[mi][h], rs[mi][h], m2, s2);
            }

    __syncthreads();                     // mainloop smem reads complete
    // stage fp16 scores: [128][STG_H] halfs, conflict-free half2 writes
    __half* stg = (__half*)smc;
    float* red  = (float*)(smc + 128*STG_H*2);   // 34816
    #pragma unroll
    for (int mi = 0; mi < 2; mi++){
        int rowL0 = wm*32 + mi*16 + g;
        int rowL1 = rowL0 + 8;
        #pragma unroll
        for (int ni = 0; ni < 8; ni++){
            int colL = wn*64 + ni*8 + 2*t4;
            *(__half2*)(stg + rowL0*STG_H + colL) = __floats2half2_rn(acc[mi][ni][0], acc[mi][ni][1]);
            *(__half2*)(stg + rowL1*STG_H + colL) = __floats2half2_rn(acc[mi][ni][2], acc[mi][ni][3]);
        }
    }
    if (t4 == 0){
        #pragma unroll
        for (int mi = 0; mi < 2; mi++)
            #pragma unroll
            for (int h = 0; h < 2; h++){
                int rl = wm*32 + mi*16 + h*8 + g;
                red[rl*4 + wn*2 + 0] = rm[mi][h];
                red[rl*4 + wn*2 + 1] = rs[mi][h];
            }
    }
    __syncthreads();
    // coalesced fp16 score writes: warp wid owns 16 rows, one uint2 (4 halfs)/lane/row
    #pragma unroll
    for (int i = 0; i < 16; i++){
        int row = wid*16 + i;
        uint2 v = *(uint2*)(stg + row*STG_H + lane*4);
        *(uint2*)(g_s + (size_t)(m0 + row)*VPAD + v0 + lane*4) = v;
    }
    if (t < 128){
        float m = red[t*4 + 0], s = red[t*4 + 1];
        lse_merge(m, s, red[t*4 + 2], red[t*4 + 3]);
        g_pmax[(size_t)(m0 + t)*NBK + nb] = m;
        g_psum[(size_t)(m0 + t)*NBK + nb] = s;
    }
}

// ---------------- kernel: combine partials -> lse per row ----------------
__global__ void k_reduce(){
    int r = blockIdx.x, t = threadIdx.x;   // 256 threads
    float m = -1e30f, s = 0.f;
    for (int p = t; p < NBK; p += 256)
        lse_merge(m, s, g_pmax[(size_t)r*NBK + p], g_psum[(size_t)r*NBK + p]);
    #pragma unroll
    for (int off = 16; off >= 1; off >>= 1){
        float m2 = __shfl_xor_sync(0xffffffffu, m, off);
        float s2 = __shfl_xor_sync(0xffffffffu, s, off);
        lse_merge(m, s, m2, s2);
    }
    __shared__ float sm_[8], ss_[8];
    int w = t >> 5;
    if ((t & 31) == 0){ sm_[w] = m; ss_[w] = s; }
    __syncthreads();
    if (t == 0){
        for (int w2 = 1; w2 < 8; w2++) lse_merge(m, s, sm_[w2], ss_[w2]);
        g_lse[r] = m + logf(s);
    }
}

// ---------------- kernel: out[r][v] = fp16_score[r][v] - lse[r] ----------------
__global__ void k_fixup(float4* __restrict__ out4){
    long i4 = (long)blockIdx.x*blockDim.x + threadIdx.x;
    long e = i4*4;
    if (e >= (long)B_*V_) return;
    int r = (int)(e / V_);
    int c = (int)(e - (long)r*V_);
    float4 v;
    if (c + 3 < V_){
        float l = g_lse[r];
        const __half* sp = g_s + (size_t)r*VPAD + c;
        v.x = __half2float(sp[0]) - l;
        v.y = __half2float(sp[1]) - l;
        v.z = __half2float(sp[2]) - l;
        v.w = __half2float(sp[3]) - l;
    } else {
        // float4 straddles a row boundary (V_ odd)
        float res[4];
        #pragma unroll
        for (int j = 0; j < 4; j++){
            int rr = r, cc = c + j;
            if (cc >= V_){ rr = r + 1; cc -= V_; }
            res[j] = __half2float(g_s[(size_t)rr*VPAD + cc]) - g_lse[rr];
        }
        v.x = res[0]; v.y = res[1]; v.z = res[2]; v.w = res[3];
    }
    out4[i4] = v;
}

// ---------------- launch ----------------
extern "C" void kernel_launch(void* const* d_in, const int* in_sizes, int n_in,
                              void* d_out, int out_size){
    const float* xs     = (const float*)d_in[0];   // [B, V]
    const float* metric = (const float*)d_in[1];   // [E, E]
    const float* emb    = (const float*)d_in[2];   // [V, E]
    const float* neg    = (const float*)d_in[3];   // [V, E]
    float* out = (float*)d_out;

    cudaFuncSetAttribute((const void*)k_pass0,
                         cudaFuncAttributeMaxDynamicSharedMemorySize, SMEM_REQ);

    k_scanprep<<<SCAN_BLOCKS + PREP_BLOCKS, 256>>>((const float4*)xs, neg);
    k_q<<<B_, E_>>>(emb, metric);
    dim3 grid(B_/128, NBK);     // mb fastest -> 8 CTAs share each B tile in L2
    k_pass0<<<grid, 256, SMEM_REQ>>>();
    k_reduce<<<B_, 256>>>();
    long n4 = ((long)B_*V_) / 4;                  // 12,865,792
    k_fixup<<<(int)((n4 + 255)/256), 256>>>((float4*)out);
}